// round 12
// baseline (speedup 1.0000x reference)
#include <cuda_runtime.h>
#include <math.h>

// SpectralCirculantLayer: y = ifft(fft(x) * H) + bias, N=4096 per row, B=8192.
// rfft-4096 via c2c-2048 (even/odd pack), spectral multiply on bins 0..1023 (H
// truncated), one-sided inverse pack, irfft via c2c-2048.
// Forward: radix 16*16*8 Stockham (unchanged from the 92.8us kernel).
// Inverse: radix 8*16*16 Stockham, with the mid stage (untangle + H multiply +
// one-sided inverse pack) FUSED into the radix-8 inverse stage 1: each thread
// processes two 8-point butterflies sequentially (v[8] liveness only, unlike
// the spilling radix-16 fusion). Saves 32 smem ops/thread/row.
// 128 threads per CTA, one row per CTA, 4 CTAs/SM, H cached in smem
// (1025 entries, Hs[1024]=0 sentinel).

#define NTHREADS 128
#define SB16 2176   // 2048 + 2048/16 padding
#define HS_N 1056   // 1025 rounded up

__device__ __forceinline__ int pd(int i) { return i + (i >> 4); }

__device__ __forceinline__ float2 cadd(float2 a, float2 b) { return make_float2(a.x + b.x, a.y + b.y); }
__device__ __forceinline__ float2 csub(float2 a, float2 b) { return make_float2(a.x - b.x, a.y - b.y); }
__device__ __forceinline__ float2 cmul(float2 a, float2 b) {
    return make_float2(fmaf(a.x, b.x, -a.y * b.y), fmaf(a.x, b.y, a.y * b.x));
}
__device__ __forceinline__ float2 conjf2(float2 a) { return make_float2(a.x, -a.y); }

template <int DIR>
__device__ __forceinline__ float2 mulJ(float2 a) {
    return (DIR < 0) ? make_float2(a.y, -a.x) : make_float2(-a.y, a.x);
}

template <int DIR>
__device__ __forceinline__ void dft4(float2* v) {
    float2 s0 = cadd(v[0], v[2]), d0 = csub(v[0], v[2]);
    float2 s1 = cadd(v[1], v[3]), d1 = mulJ<DIR>(csub(v[1], v[3]));
    v[0] = cadd(s0, s1);
    v[1] = cadd(d0, d1);
    v[2] = csub(s0, s1);
    v[3] = csub(d0, d1);
}

template <int DIR>
__device__ __forceinline__ void dft8(float2* v) {
    const float HC = 0.70710678118654752f;
    float2 b0 = cadd(v[0], v[4]);
    float2 b1 = cadd(v[1], v[5]);
    float2 b2 = cadd(v[2], v[6]);
    float2 b3 = cadd(v[3], v[7]);
    float2 c0 = csub(v[0], v[4]);
    float2 c1 = cmul(csub(v[1], v[5]), make_float2(HC, DIR * HC));
    float2 c2 = mulJ<DIR>(csub(v[2], v[6]));
    float2 c3 = cmul(csub(v[3], v[7]), make_float2(-HC, DIR * HC));
    {
        float2 s0 = cadd(b0, b2), d0 = csub(b0, b2);
        float2 s1 = cadd(b1, b3), d1 = mulJ<DIR>(csub(b1, b3));
        v[0] = cadd(s0, s1);
        v[2] = cadd(d0, d1);
        v[4] = csub(s0, s1);
        v[6] = csub(d0, d1);
    }
    {
        float2 s0 = cadd(c0, c2), d0 = csub(c0, c2);
        float2 s1 = cadd(c1, c3), d1 = mulJ<DIR>(csub(c1, c3));
        v[1] = cadd(s0, s1);
        v[3] = cadd(d0, d1);
        v[5] = csub(s0, s1);
        v[7] = csub(d0, d1);
    }
}

// 16-point DFT in registers: two radix-4 levels (Stockham, self-sorting).
template <int DIR>
__device__ __forceinline__ void dft16(float2* v) {
    const float C1 = 0.92387953251128675f;
    const float S1 = 0.38268343236508977f;
    const float H2 = 0.70710678118654752f;
    const float2 W1 = make_float2(C1, DIR * S1);
    const float2 W2 = make_float2(H2, DIR * H2);
    const float2 W3 = make_float2(S1, DIR * C1);
    const float2 W6 = make_float2(-H2, DIR * H2);
    const float2 W9 = make_float2(-C1, -DIR * S1);

    float2 u[16];
#pragma unroll
    for (int i = 0; i < 4; i++) {
        float2 a[4] = {v[i], v[i + 4], v[i + 8], v[i + 12]};
        dft4<DIR>(a);
        u[4 * i + 0] = a[0];
        u[4 * i + 1] = a[1];
        u[4 * i + 2] = a[2];
        u[4 * i + 3] = a[3];
    }
    {
        float2 a[4] = {u[0], u[4], u[8], u[12]};
        dft4<DIR>(a);
        v[0] = a[0]; v[4] = a[1]; v[8] = a[2]; v[12] = a[3];
    }
    {
        float2 a[4] = {u[1], cmul(u[5], W1), cmul(u[9], W2), cmul(u[13], W3)};
        dft4<DIR>(a);
        v[1] = a[0]; v[5] = a[1]; v[9] = a[2]; v[13] = a[3];
    }
    {
        float2 a[4] = {u[2], cmul(u[6], W2), mulJ<DIR>(u[10]), cmul(u[14], W6)};
        dft4<DIR>(a);
        v[2] = a[0]; v[6] = a[1]; v[10] = a[2]; v[14] = a[3];
    }
    {
        float2 a[4] = {u[3], cmul(u[7], W3), cmul(u[11], W6), cmul(u[15], W9)};
        dft4<DIR>(a);
        v[3] = a[0]; v[7] = a[1]; v[11] = a[2]; v[15] = a[3];
    }
}

// Fwd stage 1: radix-16, NS=1, reads global, writes padded smem.
__device__ __forceinline__ void stage_f1(const float2* __restrict__ in,
                                         float2* __restrict__ out, int tl) {
    float2 v[16];
#pragma unroll
    for (int r = 0; r < 16; r++) v[r] = in[tl + (r << 7)];
    dft16<-1>(v);
#pragma unroll
    for (int r = 0; r < 16; r++) out[pd((tl << 4) + r)] = v[r];
}

// Fwd stage 2: radix-16, NS=16. Serial twiddle chain.
__device__ __forceinline__ void stage_f2(const float2* __restrict__ in,
                                         float2* __restrict__ out, int tl, float2 wb) {
    float2 v[16];
#pragma unroll
    for (int r = 0; r < 16; r++) v[r] = in[pd(tl + (r << 7))];
    float2 wr = wb;
    v[1] = cmul(v[1], wr);
#pragma unroll
    for (int r = 2; r < 16; r++) {
        wr = cmul(wr, wb);
        v[r] = cmul(v[r], wr);
    }
    dft16<-1>(v);
    const int jm = tl & 15, jd = tl >> 4;
    const int o = (jd << 8) + jm;
#pragma unroll
    for (int r = 0; r < 16; r++) out[pd(o + (r << 4))] = v[r];
}

// Fwd stage 3: radix-8, NS=256. Two butterflies per thread (j = tl, tl+128).
__device__ __forceinline__ void stage_f3(const float2* __restrict__ in,
                                         float2* __restrict__ out, int tl,
                                         float2 wA, float2 wB) {
#pragma unroll
    for (int h = 0; h < 2; h++) {
        const int j = tl + (h << 7);
        const float2 wb = h ? wB : wA;
        float2 v[8];
#pragma unroll
        for (int r = 0; r < 8; r++) v[r] = in[pd(j + (r << 8))];
        float2 wr = wb;
        v[1] = cmul(v[1], wr);
#pragma unroll
        for (int r = 2; r < 8; r++) {
            wr = cmul(wr, wb);
            v[r] = cmul(v[r], wr);
        }
        dft8<-1>(v);
#pragma unroll
        for (int r = 0; r < 8; r++) out[pd(j + (r << 8))] = v[r];
    }
}

// FUSED mid + inverse stage 1 (radix-8, NS=1). Two butterflies per thread,
// processed sequentially (v[8] liveness). Butterfly j needs D[j+256r]:
//  k < 1024:  D[k] = Y[k]*(1+wq.y, wq.x),       Y[k] = X[k]*H[k]*sc
//  k >= 1024: D[k] = conj(Y[mk])*(1-wqm.y,wqm.x), mk = 2048-k, wqm = (-wq.x, wq.y)
// where X[k] untangled from forward outputs Z[k], Z[2048-k]; wq = e^{-2pi*i*k/4096}.
// Hs[1024] = 0 makes the k==1024 bin vanish branchlessly.
__device__ __forceinline__ void fused_mid_inv1(const float2* __restrict__ Z,
                                               float2* __restrict__ out,
                                               const float2* __restrict__ Hs,
                                               int tl, float2 wqb) {
    // MC8[r] = e^{-i*pi*r/8}
    const float MCC[8] = {1.0f, 0.92387953251128675f, 0.70710678118654752f, 0.38268343236508977f,
                          0.0f, -0.38268343236508977f, -0.70710678118654752f, -0.92387953251128675f};
    const float MCS[8] = {0.0f, -0.38268343236508977f, -0.70710678118654752f, -0.92387953251128675f,
                          -1.0f, -0.92387953251128675f, -0.70710678118654752f, -0.38268343236508977f};
    const float2 E16 = make_float2(0.98078528040323044f, -0.19509032201612827f);  // e^{-i*pi/16}
    const float SC = 1.0f / 4096.0f;  // 0.5 (pack) * 1/2048 (IDFT)
#pragma unroll
    for (int h = 0; h < 2; h++) {
        const int j = tl + (h << 7);
        const float2 wqbase = h ? cmul(wqb, E16) : wqb;  // e^{-2pi*i*j/4096}
        float2 v[8];
#pragma unroll
        for (int r = 0; r < 8; r++) {
            const int k = j + (r << 8);
            const float2 wq = cmul(wqbase, make_float2(MCC[r], MCS[r]));  // e^{-2pi*i*k/4096}
            if (r < 4) {
                // k = j + 256r <= 255+768 < 1024
                float2 a = Z[pd(k)];
                float2 b = Z[pd((2048 - k) & 2047)];
                float2 E = make_float2(0.5f * (a.x + b.x), 0.5f * (a.y - b.y));
                float2 O = make_float2(0.5f * (a.y + b.y), -0.5f * (a.x - b.x));
                float2 X = cadd(E, cmul(O, wq));
                float2 Yk = cmul(X, Hs[k]);
                Yk.x *= SC;
                Yk.y *= SC;
                v[r] = cmul(Yk, make_float2(1.0f + wq.y, wq.x));
            } else {
                // k >= 1024; mirror bin mk = 2048-k in [1, 1024]
                const int mk = 2048 - k;
                const float2 wqm = make_float2(-wq.x, wq.y);  // e^{-2pi*i*mk/4096}
                float2 a = Z[pd(mk)];
                float2 b = Z[pd(k)];  // 2048-mk = k (< 2048)
                float2 E = make_float2(0.5f * (a.x + b.x), 0.5f * (a.y - b.y));
                float2 O = make_float2(0.5f * (a.y + b.y), -0.5f * (a.x - b.x));
                float2 X = cadd(E, cmul(O, wqm));
                float2 Ym = cmul(X, Hs[mk]);  // Hs[1024] = 0 sentinel
                Ym.x *= SC;
                Ym.y *= SC;
                float2 Yc = conjf2(Ym);
                v[r] = cmul(Yc, make_float2(1.0f - wqm.y, wqm.x));
            }
        }
        dft8<1>(v);
        const int o = j << 3;
#pragma unroll
        for (int r = 0; r < 8; r++) out[pd(o + r)] = v[r];
    }
}

// Inverse stage 2: radix-16, NS=8. wb = e^{+2pi*i*(tl&7)/128}.
__device__ __forceinline__ void stage_i2(const float2* __restrict__ in,
                                         float2* __restrict__ out, int tl, float2 wb) {
    float2 v[16];
#pragma unroll
    for (int r = 0; r < 16; r++) v[r] = in[pd(tl + (r << 7))];
    float2 wr = wb;
    v[1] = cmul(v[1], wr);
#pragma unroll
    for (int r = 2; r < 16; r++) {
        wr = cmul(wr, wb);
        v[r] = cmul(v[r], wr);
    }
    dft16<1>(v);
    const int jm = tl & 7, jd = tl >> 3;
    const int o = (jd << 7) + jm;
#pragma unroll
    for (int r = 0; r < 16; r++) out[pd(o + (r << 3))] = v[r];
}

// Inverse stage 3: radix-16, NS=128, writes global with bias.
// wb = e^{+2pi*i*tl/2048}.
__device__ __forceinline__ void stage_i3(const float2* __restrict__ in,
                                         float2* __restrict__ out, int tl,
                                         float2 wb, float bv) {
    float2 v[16];
#pragma unroll
    for (int r = 0; r < 16; r++) v[r] = in[pd(tl + (r << 7))];
    float2 wr = wb;
    v[1] = cmul(v[1], wr);
#pragma unroll
    for (int r = 2; r < 16; r++) {
        wr = cmul(wr, wb);
        v[r] = cmul(v[r], wr);
    }
    dft16<1>(v);
#pragma unroll
    for (int r = 0; r < 16; r++)
        out[tl + (r << 7)] = make_float2(v[r].x + bv, v[r].y + bv);
}

__global__ void __launch_bounds__(NTHREADS, 4)
spectral_circulant_kernel(const float* __restrict__ x, const float* __restrict__ wre,
                          const float* __restrict__ wim, const float* __restrict__ bias,
                          float* __restrict__ out, int nrows) {
    extern __shared__ float2 sm[];
    float2* X = sm;
    float2* Y = sm + SB16;
    float2* Hs = sm + 2 * SB16;  // 1025 entries, Hs[1024] = 0
    const int tl = threadIdx.x;  // 0..127

    for (int k = tl; k < 1025; k += NTHREADS)
        Hs[k] = (k < 1024) ? make_float2(__ldg(wre + k), __ldg(wim + k)) : make_float2(0.0f, 0.0f);
    const float bv = __ldg(bias);

    // Per-thread row-invariant twiddle bases
    float s, c;
    sincospif(-(float)(tl & 15) * (1.0f / 128.0f), &s, &c);
    const float2 w2f = make_float2(c, s);   // fwd s2: e^{-2pi*i*(tl&15)/256}
    sincospif(-(float)tl * (1.0f / 1024.0f), &s, &c);
    const float2 w3f = make_float2(c, s);   // fwd s3 (j=tl): e^{-2pi*i*tl/2048}
    sincospif(-(float)tl * (1.0f / 2048.0f), &s, &c);
    const float2 wqb = make_float2(c, s);   // mid base: e^{-2pi*i*tl/4096}
    sincospif((float)(tl & 7) * (1.0f / 64.0f), &s, &c);
    const float2 w2n = make_float2(c, s);   // inv s2: e^{+2pi*i*(tl&7)/128}
    const float2 E8 = make_float2(0.92387953251128675f, -0.38268343236508977f);  // e^{-i*pi/8}
    const float2 w3g = cmul(w3f, E8);       // fwd s3 (j=tl+128)
    const float2 w3i = conjf2(w3f);         // inv s3: e^{+2pi*i*tl/2048}
    __syncthreads();  // Hs visible

    for (int row = blockIdx.x; row < nrows; row += gridDim.x) {
        const float2* xin = reinterpret_cast<const float2*>(x) + (size_t)row * 2048;
        float2* yout = reinterpret_cast<float2*>(out) + (size_t)row * 2048;

        // Forward c2c-2048: G -> Y -> X -> Y
        stage_f1(xin, Y, tl);
        __syncthreads();
        stage_f2(Y, X, tl, w2f);
        __syncthreads();
        stage_f3(X, Y, tl, w3f, w3g);
        __syncthreads();

        // Fused mid + inverse stage 1 (radix-8): Y -> X
        fused_mid_inv1(Y, X, Hs, tl, wqb);
        __syncthreads();

        // Inverse stages 2 (X -> Y), 3 (Y -> G)
        stage_i2(X, Y, tl, w2n);
        __syncthreads();
        stage_i3(Y, yout, tl, w3i, bv);
        __syncthreads();  // i3 reads Y; next row's stage_f1 writes Y
    }
}

extern "C" void kernel_launch(void* const* d_in, const int* in_sizes, int n_in,
                              void* d_out, int out_size) {
    const float* x = (const float*)d_in[0];
    const float* wre = (const float*)d_in[1];
    const float* wim = (const float*)d_in[2];
    const float* bias = (const float*)d_in[3];
    float* out = (float*)d_out;

    const int nrows = in_sizes[0] / 4096;  // 8192
    const int smem_bytes = (2 * SB16 + HS_N) * sizeof(float2);  // 43264

    static int grid = 0;
    if (grid == 0) {
        cudaFuncSetAttribute(spectral_circulant_kernel,
                             cudaFuncAttributeMaxDynamicSharedMemorySize, smem_bytes);
        int nsm = 148;
        cudaDeviceGetAttribute(&nsm, cudaDevAttrMultiProcessorCount, 0);
        grid = 4 * nsm;  // persistent, 4 CTAs/SM (1 row each)
    }

    spectral_circulant_kernel<<<grid, NTHREADS, smem_bytes>>>(x, wre, wim, bias, out, nrows);
}

// round 13
// speedup vs baseline: 1.1767x; 1.1767x over previous
#include <cuda_runtime.h>
#include <math.h>

// SpectralCirculantLayer: y = ifft(fft(x) * H) + bias, N=4096 per row, B=8192.
// rfft-4096 via c2c-2048 (even/odd pack), spectral multiply on bins 0..1023 (H
// truncated), one-sided inverse pack, irfft via c2c-2048.
// Radix 16*16*8 Stockham (3 smem stages per direction), 128 threads per CTA,
// ONE row per CTA, 4 CTAs/SM, separate midstage, H in smem (the 92.8us R10
// structure). THIS ROUND (issue-slot reduction, ~zero liveness delta):
//  1) padding i+2*(i>>4) (16B-aligned rows) so stage-1 smem writes use
//     STS.128 (16 -> 8 stores in fwd-s1 and inv-s1), all patterns re-audited
//     conflict-free per half-warp;
//  2) dual-chain twiddle powers (odd/even chains via w^2): critical path
//     15->8 cmuls (stage 2), 7->4 (stage 3), +2 regs only.

#define NTHREADS 128
#define SB16 2304   // 2048 + 2*(2048/16) padding (stride-18 rows, 16B aligned)

__device__ __forceinline__ int pd(int i) { return i + ((i >> 4) << 1); }

__device__ __forceinline__ float2 cadd(float2 a, float2 b) { return make_float2(a.x + b.x, a.y + b.y); }
__device__ __forceinline__ float2 csub(float2 a, float2 b) { return make_float2(a.x - b.x, a.y - b.y); }
__device__ __forceinline__ float2 cmul(float2 a, float2 b) {
    return make_float2(fmaf(a.x, b.x, -a.y * b.y), fmaf(a.x, b.y, a.y * b.x));
}
__device__ __forceinline__ float2 conjf2(float2 a) { return make_float2(a.x, -a.y); }

template <int DIR>
__device__ __forceinline__ float2 mulJ(float2 a) {
    return (DIR < 0) ? make_float2(a.y, -a.x) : make_float2(-a.y, a.x);
}

template <int DIR>
__device__ __forceinline__ void dft4(float2* v) {
    float2 s0 = cadd(v[0], v[2]), d0 = csub(v[0], v[2]);
    float2 s1 = cadd(v[1], v[3]), d1 = mulJ<DIR>(csub(v[1], v[3]));
    v[0] = cadd(s0, s1);
    v[1] = cadd(d0, d1);
    v[2] = csub(s0, s1);
    v[3] = csub(d0, d1);
}

template <int DIR>
__device__ __forceinline__ void dft8(float2* v) {
    const float HC = 0.70710678118654752f;
    float2 b0 = cadd(v[0], v[4]);
    float2 b1 = cadd(v[1], v[5]);
    float2 b2 = cadd(v[2], v[6]);
    float2 b3 = cadd(v[3], v[7]);
    float2 c0 = csub(v[0], v[4]);
    float2 c1 = cmul(csub(v[1], v[5]), make_float2(HC, DIR * HC));
    float2 c2 = mulJ<DIR>(csub(v[2], v[6]));
    float2 c3 = cmul(csub(v[3], v[7]), make_float2(-HC, DIR * HC));
    {
        float2 s0 = cadd(b0, b2), d0 = csub(b0, b2);
        float2 s1 = cadd(b1, b3), d1 = mulJ<DIR>(csub(b1, b3));
        v[0] = cadd(s0, s1);
        v[2] = cadd(d0, d1);
        v[4] = csub(s0, s1);
        v[6] = csub(d0, d1);
    }
    {
        float2 s0 = cadd(c0, c2), d0 = csub(c0, c2);
        float2 s1 = cadd(c1, c3), d1 = mulJ<DIR>(csub(c1, c3));
        v[1] = cadd(s0, s1);
        v[3] = cadd(d0, d1);
        v[5] = csub(s0, s1);
        v[7] = csub(d0, d1);
    }
}

// 16-point DFT in registers: two radix-4 levels (Stockham, self-sorting).
template <int DIR>
__device__ __forceinline__ void dft16(float2* v) {
    const float C1 = 0.92387953251128675f;
    const float S1 = 0.38268343236508977f;
    const float H2 = 0.70710678118654752f;
    const float2 W1 = make_float2(C1, DIR * S1);
    const float2 W2 = make_float2(H2, DIR * H2);
    const float2 W3 = make_float2(S1, DIR * C1);
    const float2 W6 = make_float2(-H2, DIR * H2);
    const float2 W9 = make_float2(-C1, -DIR * S1);

    float2 u[16];
#pragma unroll
    for (int i = 0; i < 4; i++) {
        float2 a[4] = {v[i], v[i + 4], v[i + 8], v[i + 12]};
        dft4<DIR>(a);
        u[4 * i + 0] = a[0];
        u[4 * i + 1] = a[1];
        u[4 * i + 2] = a[2];
        u[4 * i + 3] = a[3];
    }
    {
        float2 a[4] = {u[0], u[4], u[8], u[12]};
        dft4<DIR>(a);
        v[0] = a[0]; v[4] = a[1]; v[8] = a[2]; v[12] = a[3];
    }
    {
        float2 a[4] = {u[1], cmul(u[5], W1), cmul(u[9], W2), cmul(u[13], W3)};
        dft4<DIR>(a);
        v[1] = a[0]; v[5] = a[1]; v[9] = a[2]; v[13] = a[3];
    }
    {
        float2 a[4] = {u[2], cmul(u[6], W2), mulJ<DIR>(u[10]), cmul(u[14], W6)};
        dft4<DIR>(a);
        v[2] = a[0]; v[6] = a[1]; v[10] = a[2]; v[14] = a[3];
    }
    {
        float2 a[4] = {u[3], cmul(u[7], W3), cmul(u[11], W6), cmul(u[15], W9)};
        dft4<DIR>(a);
        v[3] = a[0]; v[7] = a[1]; v[11] = a[2]; v[15] = a[3];
    }
}

// Stage 1: radix-16, NS=1. tl = 0..127. Reads global (GIN) or padded smem.
// Output pd(16*tl+r) = 18*tl+r is contiguous -> vectorized STS.128.
template <int DIR, bool GIN>
__device__ __forceinline__ void stage_r16_ns1(const float2* __restrict__ in,
                                              float2* __restrict__ out, int tl) {
    float2 v[16];
#pragma unroll
    for (int r = 0; r < 16; r++) v[r] = GIN ? in[tl + (r << 7)] : in[pd(tl + (r << 7))];
    dft16<DIR>(v);
    float4* __restrict__ o4 = reinterpret_cast<float4*>(out) + 9 * tl;  // (18*tl)/2
#pragma unroll
    for (int q = 0; q < 8; q++)
        o4[q] = make_float4(v[2 * q].x, v[2 * q].y, v[2 * q + 1].x, v[2 * q + 1].y);
}

// Stage 2: radix-16, NS=16. Dual-chain twiddle powers (odd/even via w^2).
template <int DIR>
__device__ __forceinline__ void stage_r16_ns16(const float2* __restrict__ in,
                                               float2* __restrict__ out, int tl, float2 wb) {
    float2 v[16];
#pragma unroll
    for (int r = 0; r < 16; r++) v[r] = in[pd(tl + (r << 7))];
    {
        float2 p2 = cmul(wb, wb);
        float2 wo = wb;   // odd-power chain: w^1, w^3, ...
        float2 we = p2;   // even-power chain: w^2, w^4, ...
        v[1] = cmul(v[1], wo);
        v[2] = cmul(v[2], we);
#pragma unroll
        for (int r = 3; r < 16; r += 2) {
            wo = cmul(wo, p2);
            v[r] = cmul(v[r], wo);
            if (r + 1 < 16) {
                we = cmul(we, p2);
                v[r + 1] = cmul(v[r + 1], we);
            }
        }
    }
    dft16<DIR>(v);
    const int jm = tl & 15, jd = tl >> 4;
    const int o = (jd << 8) + jm;
#pragma unroll
    for (int r = 0; r < 16; r++) out[pd(o + (r << 4))] = v[r];
}

// Stage 3: radix-8, NS=256. Two butterflies per thread (j = tl, tl+128).
// Dual-chain twiddles. GOUT: write to global with bias add (coalesced).
template <int DIR, bool GOUT>
__device__ __forceinline__ void stage_r8_ns256(const float2* __restrict__ in,
                                               float2* __restrict__ out, int tl,
                                               float2 wA, float2 wB, float bv) {
#pragma unroll
    for (int h = 0; h < 2; h++) {
        const int j = tl + (h << 7);
        const float2 wb = h ? wB : wA;
        float2 v[8];
#pragma unroll
        for (int r = 0; r < 8; r++) v[r] = in[pd(j + (r << 8))];
        {
            float2 p2 = cmul(wb, wb);
            float2 wo = wb;
            float2 we = p2;
            v[1] = cmul(v[1], wo);
            v[2] = cmul(v[2], we);
            wo = cmul(wo, p2); v[3] = cmul(v[3], wo);
            we = cmul(we, p2); v[4] = cmul(v[4], we);
            wo = cmul(wo, p2); v[5] = cmul(v[5], wo);
            we = cmul(we, p2); v[6] = cmul(v[6], we);
            wo = cmul(wo, p2); v[7] = cmul(v[7], wo);
        }
        dft8<DIR>(v);
#pragma unroll
        for (int r = 0; r < 8; r++) {
            if (GOUT)
                out[j + (r << 8)] = make_float2(v[r].x + bv, v[r].y + bv);
            else
                out[pd(j + (r << 8))] = v[r];
        }
    }
}

// Untangle rfft, multiply by H, repack one-sided for inverse. wqb = e^{-2pi*i*tl/4096}.
__device__ __forceinline__ void midstage(const float2* __restrict__ S, float2* __restrict__ D,
                                         const float2* __restrict__ Hs, int tl, float2 wqb) {
    // MC[i] = e^{-pi*i*i/16}
    const float MCC[8] = {1.0f, 0.98078528040323044f, 0.92387953251128675f, 0.83146961230254524f,
                          0.70710678118654752f, 0.55557023301960222f, 0.38268343236508977f, 0.19509032201612827f};
    const float MCS[8] = {0.0f, -0.19509032201612827f, -0.38268343236508977f, -0.55557023301960222f,
                          -0.70710678118654752f, -0.83146961230254524f, -0.92387953251128675f, -0.98078528040323044f};
#pragma unroll
    for (int i = 0; i < 8; i++) {
        const int k = tl + (i << 7);
        const float2 wq = cmul(wqb, make_float2(MCC[i], MCS[i]));  // e^{-2pi*i*k/4096}
        float2 Zk = S[pd(k)];
        float2 Zm = S[pd((2048 - k) & 2047)];
        float2 E = make_float2(0.5f * (Zk.x + Zm.x), 0.5f * (Zk.y - Zm.y));
        float2 O = make_float2(0.5f * (Zk.y + Zm.y), -0.5f * (Zk.x - Zm.x));
        float2 Xk = cadd(E, cmul(O, wq));
        float2 Hk = Hs[k];
        float2 Yk = cmul(Xk, Hk);
        const float sc = 1.0f / 4096.0f;  // 0.5 (pack) * 1/2048 (IDFT)
        Yk.x *= sc;
        Yk.y *= sc;
        const float cph = wq.x, sph = -wq.y;
        D[pd(k)] = cmul(Yk, make_float2(1.0f - sph, cph));
        if (k > 0) {
            float2 Yc = make_float2(Yk.x, -Yk.y);
            D[pd(2048 - k)] = cmul(Yc, make_float2(1.0f + sph, cph));
        } else {
            D[pd(1024)] = make_float2(0.0f, 0.0f);
        }
    }
}

__global__ void __launch_bounds__(NTHREADS, 4)
spectral_circulant_kernel(const float* __restrict__ x, const float* __restrict__ wre,
                          const float* __restrict__ wim, const float* __restrict__ bias,
                          float* __restrict__ out, int nrows) {
    extern __shared__ float2 sm[];
    float2* X = sm;
    float2* Y = sm + SB16;
    float2* Hs = sm + 2 * SB16;  // 1024 float2
    const int tl = threadIdx.x;  // 0..127

    // One-time: cache H in smem
    for (int k = tl; k < 1024; k += NTHREADS) Hs[k] = make_float2(__ldg(wre + k), __ldg(wim + k));
    const float bv = __ldg(bias);

    // Per-thread twiddle bases (row-invariant)
    float s, c;
    sincospif(-(float)(tl & 15) * (1.0f / 128.0f), &s, &c);
    const float2 w2f = make_float2(c, s);  // e^{-2pi*i*(tl&15)/256}
    sincospif(-(float)tl * (1.0f / 1024.0f), &s, &c);
    const float2 w3f = make_float2(c, s);  // e^{-2pi*i*tl/2048}
    sincospif(-(float)tl * (1.0f / 2048.0f), &s, &c);
    const float2 wqb = make_float2(c, s);  // e^{-2pi*i*tl/4096}
    const float2 E8 = make_float2(0.92387953251128675f, -0.38268343236508977f);  // e^{-i*pi/8}
    const float2 w3g = cmul(w3f, E8);
    const float2 w2i = conjf2(w2f);
    const float2 w3i = conjf2(w3f);
    const float2 w3gi = conjf2(w3g);
    __syncthreads();  // Hs visible

    for (int row = blockIdx.x; row < nrows; row += gridDim.x) {
        const float2* xin = reinterpret_cast<const float2*>(x) + (size_t)row * 2048;
        float2* yout = reinterpret_cast<float2*>(out) + (size_t)row * 2048;

        // Forward c2c-2048: G -> Y -> X -> Y
        stage_r16_ns1<-1, true>(xin, Y, tl);
        __syncthreads();
        stage_r16_ns16<-1>(Y, X, tl, w2f);
        __syncthreads();
        stage_r8_ns256<-1, false>(X, Y, tl, w3f, w3g, 0.0f);
        __syncthreads();

        // Mid: Y -> X
        midstage(Y, X, Hs, tl, wqb);
        __syncthreads();

        // Inverse c2c-2048: X -> Y -> X -> G
        stage_r16_ns1<1, false>(X, Y, tl);
        __syncthreads();
        stage_r16_ns16<1>(Y, X, tl, w2i);
        __syncthreads();
        stage_r8_ns256<1, true>(X, yout, tl, w3i, w3gi, bv);
        // no trailing barrier: this stage's X reads precede the barrier after
        // the next row's stage 1 (which writes Y); X is next written only
        // after a later barrier.
    }
}

extern "C" void kernel_launch(void* const* d_in, const int* in_sizes, int n_in,
                              void* d_out, int out_size) {
    const float* x = (const float*)d_in[0];
    const float* wre = (const float*)d_in[1];
    const float* wim = (const float*)d_in[2];
    const float* bias = (const float*)d_in[3];
    float* out = (float*)d_out;

    const int nrows = in_sizes[0] / 4096;  // 8192
    const int smem_bytes = (2 * SB16 + 1024) * sizeof(float2);  // 45056

    static int grid = 0;
    if (grid == 0) {
        cudaFuncSetAttribute(spectral_circulant_kernel,
                             cudaFuncAttributeMaxDynamicSharedMemorySize, smem_bytes);
        int nsm = 148;
        cudaDeviceGetAttribute(&nsm, cudaDevAttrMultiProcessorCount, 0);
        grid = 4 * nsm;  // persistent, 4 CTAs/SM (1 row each)
    }

    spectral_circulant_kernel<<<grid, NTHREADS, smem_bytes>>>(x, wre, wim, bias, out, nrows);
}